// round 15
// baseline (speedup 1.0000x reference)
#include <cuda_runtime.h>
#include <cuda_bf16.h>
#include <cstdint>

// CommNetLSTM: B=4096, N=32, OBS=128, H=64, A=16
// One CTA per batch. All agent state in smem. f32x2 packed-FMA GEMMs.
// Gates GEMM tiled 16 rows x 2 cols per thread (cols p, p+128).
//
// Output layout (flattened, reference tuple order):
//   [0, B*N*A)    logits | [..+B*N) values | [..+B*N*H) h | [..+B*N*H) c

#define Bsz 4096
#define Nag 32
#define OBSD 128
#define Hd 64
#define Ad 16
#define ST 36       // col-major column stride (padded, mult of 4; 144B = 16B-aligned)
#define GST 257     // gates row stride (odd -> conflict-free LSTM reads)
#define HRST 65     // h_rm/c_rm row stride

#define OFF_VAL  (2097152)
#define OFF_H    (2097152 + 131072)
#define OFF_C    (OFF_H + 8388608)

// smem offsets (floats)
#define X_CM   0              // 64*36 x col-major [hc][r]
#define H_CM   2304           // 64*36
#define Z_CM   4608           // 64*36
#define H_RM   6912           // 32*65
#define C_RM   8992           // 32*65
#define S_OFF  11072          // 64
#define SCR    11136          // obs_cm 128*36=4608; later comm_cm 64*36
#define G_OFF  (SCR + 4608)   // gates 32*257 = 8224
#define SMEM_FLOATS (G_OFF + 8224)   // 23968 floats = 95872 B

typedef unsigned long long ull;

__device__ __forceinline__ ull pack2(float lo, float hi) {
    ull r; asm("mov.b64 %0, {%1, %2};" : "=l"(r) : "f"(lo), "f"(hi)); return r;
}
__device__ __forceinline__ float2 unpack2(ull v) {
    float2 f; asm("mov.b64 {%0, %1}, %2;" : "=f"(f.x), "=f"(f.y) : "l"(v)); return f;
}
__device__ __forceinline__ void ffma2(ull& d, ull a, ull b) {
    asm("fma.rn.f32x2 %0, %1, %2, %0;" : "+l"(d) : "l"(a), "l"(b));
}

__device__ __forceinline__ float sigf(float x) {
    return __fdividef(1.0f, 1.0f + __expf(-x));
}
__device__ __forceinline__ float tanhf_fast(float x) {
    return 1.0f - __fdividef(2.0f, __expf(2.0f * x) + 1.0f);
}

// 8-row x 1-col accumulate: acc[4] f32x2 cover rows base..base+7.
// vals: smem col-major stride ST (broadcast reads). W: [K][Hd] row-major.
template<int K>
__device__ __forceinline__ void gemm_rows8(ull acc[4], const float* __restrict__ W,
                                           const float* vals, int base, int col) {
    #pragma unroll 8
    for (int k = 0; k < K; k++) {
        const float w = W[k * Hd + col];
        const ull wp = pack2(w, w);
        const ulonglong2 v0 = *(const ulonglong2*)&vals[k * ST + base];
        const ulonglong2 v1 = *(const ulonglong2*)&vals[k * ST + base + 4];
        ffma2(acc[0], v0.x, wp);
        ffma2(acc[1], v0.y, wp);
        ffma2(acc[2], v1.x, wp);
        ffma2(acc[3], v1.y, wp);
    }
}

// Single-matrix gates accumulate: 16 rows x 2 cols (p, p+128), K=64.
__device__ __forceinline__ void gemm_gates2(ull accA[8], ull accB[8],
                                            const float* __restrict__ W,
                                            const float* vals, int p, int rbase) {
    #pragma unroll 8
    for (int k = 0; k < Hd; k++) {
        const float wa = W[k * 256 + p];
        const float wb = W[k * 256 + p + 128];
        const ull wpa = pack2(wa, wa);
        const ull wpb = pack2(wb, wb);
        #pragma unroll
        for (int q = 0; q < 4; q++) {
            const ulonglong2 v = *(const ulonglong2*)&vals[k * ST + rbase + q * 4];
            ffma2(accA[2 * q],     v.x, wpa);
            ffma2(accA[2 * q + 1], v.y, wpa);
            ffma2(accB[2 * q],     v.x, wpb);
            ffma2(accB[2 * q + 1], v.y, wpb);
        }
    }
}

// Fused dual-matrix gates accumulate for hop 1: interleaves Wx (over z) and
// Wh (over h) per k-step so both weight LDG streams stay in flight together.
__device__ __forceinline__ void gemm_gates2_dual(ull accA[8], ull accB[8],
                                                 const float* __restrict__ Wx,
                                                 const float* __restrict__ Wh,
                                                 const float* zv, const float* hv,
                                                 int p, int rbase) {
    #pragma unroll 4
    for (int k = 0; k < Hd; k++) {
        const float wxa = Wx[k * 256 + p];
        const float wxb = Wx[k * 256 + p + 128];
        const float wha = Wh[k * 256 + p];
        const float whb = Wh[k * 256 + p + 128];
        const ull wxpa = pack2(wxa, wxa);
        const ull wxpb = pack2(wxb, wxb);
        const ull whpa = pack2(wha, wha);
        const ull whpb = pack2(whb, whb);
        #pragma unroll
        for (int q = 0; q < 4; q++) {
            const ulonglong2 vz = *(const ulonglong2*)&zv[k * ST + rbase + q * 4];
            const ulonglong2 vh = *(const ulonglong2*)&hv[k * ST + rbase + q * 4];
            ffma2(accA[2 * q],     vz.x, wxpa);
            ffma2(accA[2 * q + 1], vz.y, wxpa);
            ffma2(accB[2 * q],     vz.x, wxpb);
            ffma2(accB[2 * q + 1], vz.y, wxpb);
            ffma2(accA[2 * q],     vh.x, whpa);
            ffma2(accA[2 * q + 1], vh.y, whpa);
            ffma2(accB[2 * q],     vh.x, whpb);
            ffma2(accB[2 * q + 1], vh.y, whpb);
        }
    }
}

__device__ __forceinline__ void store_gates2(float* sm, const ull accA[8],
                                             const ull accB[8], int p, int rbase) {
    #pragma unroll
    for (int q = 0; q < 8; q++) {
        const float2 fa = unpack2(accA[q]);
        const float2 fb = unpack2(accB[q]);
        const int r = rbase + 2 * q;
        sm[G_OFF + r * GST + p]             = fa.x;
        sm[G_OFF + (r + 1) * GST + p]       = fa.y;
        sm[G_OFF + r * GST + p + 128]       = fb.x;
        sm[G_OFF + (r + 1) * GST + p + 128] = fb.y;
    }
}

__global__ void __launch_bounds__(256, 2) commnet_kernel(
    const float* __restrict__ obs,
    const float* __restrict__ encW, const float* __restrict__ encb,
    const float* __restrict__ mW0,  const float* __restrict__ mb0,
    const float* __restrict__ mW1,  const float* __restrict__ mb1,
    const float* __restrict__ Wx0,  const float* __restrict__ Wh0, const float* __restrict__ lb0,
    const float* __restrict__ Wx1,  const float* __restrict__ Wh1, const float* __restrict__ lb1,
    const float* __restrict__ actW, const float* __restrict__ actb,
    const float* __restrict__ valW, const float* __restrict__ valb,
    float* __restrict__ out)
{
    extern __shared__ float sm[];
    const int b   = blockIdx.x;
    const int tid = threadIdx.x;

    // ---- P0: stage obs -> obs_cm[k*ST + r] ----
    {
        const int r = tid & 31;
        const int chunk = tid >> 5;
        const float4* src = (const float4*)(obs + (size_t)b * (Nag * OBSD) + r * OBSD);
        #pragma unroll
        for (int q = 0; q < 4; q++) {
            const float4 v = src[chunk * 4 + q];
            const int k = chunk * 16 + q * 4;
            sm[SCR + (k + 0) * ST + r] = v.x;
            sm[SCR + (k + 1) * ST + r] = v.y;
            sm[SCR + (k + 2) * ST + r] = v.z;
            sm[SCR + (k + 3) * ST + r] = v.w;
        }
    }
    __syncthreads();

    const int hc    = tid & 63;
    const int base  = (tid >> 6) * 8;
    const int p     = tid & 127;     // gates col pair: p, p+128
    const int rbase = (tid >> 7) * 16;

    // ---- P1: encoder  x = tanh(obs @ encW + encb); also z0 = x + mb0 ----
    {
        ull acc[4] = {0ull, 0ull, 0ull, 0ull};
        gemm_rows8<OBSD>(acc, encW, sm + SCR, base, hc);
        const float eb = encb[hc];
        const float zb = mb0[hc];
        #pragma unroll
        for (int q = 0; q < 4; q++) {
            const float2 f = unpack2(acc[q]);
            const int r0 = base + 2 * q;
            const float x0 = tanhf_fast(f.x + eb);
            const float x1 = tanhf_fast(f.y + eb);
            sm[X_CM + hc * ST + r0]     = x0;
            sm[X_CM + hc * ST + r0 + 1] = x1;
            sm[Z_CM + hc * ST + r0]     = x0 + zb;
            sm[Z_CM + hc * ST + r0 + 1] = x1 + zb;
        }
    }
    __syncthreads();

    // ---- hop 0: gates = z @ Wx0 + lb0 (h=0 -> Wh0 term vanishes) ----
    {
        ull accA[8], accB[8];
        const ull ba = pack2(lb0[p], lb0[p]);
        const ull bb = pack2(lb0[p + 128], lb0[p + 128]);
        #pragma unroll
        for (int q = 0; q < 8; q++) { accA[q] = ba; accB[q] = bb; }
        gemm_gates2(accA, accB, Wx0, sm + Z_CM, p, rbase);
        store_gates2(sm, accA, accB, p, rbase);
    }
    __syncthreads();

    // LSTM0 (c_old = 0)
    {
        const int r   = tid & 31;
        const int hcb = (tid >> 5) * 8;
        #pragma unroll
        for (int u = 0; u < 8; u++) {
            const int c = hcb + u;
            const float gi = sm[G_OFF + r * GST + c];
            const float gg = sm[G_OFF + r * GST + 128 + c];
            const float go = sm[G_OFF + r * GST + 192 + c];
            const float z  = sm[Z_CM + c * ST + r];
            const float cnew = sigf(gi) * tanhf_fast(gg);
            const float hnew = sigf(go) * tanhf_fast(cnew);
            const float hr   = tanhf_fast(hnew + z);
            sm[H_CM + c * ST + r]   = hr;
            sm[H_RM + r * HRST + c] = hr;
            sm[C_RM + r * HRST + c] = cnew;
        }
    }
    __syncthreads();

    // ---- hop 1: column sums of h (rotation by tid: conflict-free) ----
    if (tid < Hd) {
        float s = 0.0f;
        #pragma unroll
        for (int j = 0; j < Nag; j++) {
            const int jj = (j + tid) & 31;
            s += sm[H_CM + tid * ST + jj];
        }
        sm[S_OFF + tid] = s;
    }
    __syncthreads();

    // comm_cm[k][r] = (S[k] - h[k][r]) / 31
    {
        const float inv = 1.0f / 31.0f;
        #pragma unroll
        for (int u = 0; u < 8; u++) {
            const int idx = u * 256 + tid;   // warp-uniform k, lane r
            const int k = idx >> 5, r = idx & 31;
            sm[SCR + k * ST + r] = (sm[S_OFF + k] - sm[H_CM + k * ST + r]) * inv;
        }
    }
    __syncthreads();

    // z = x + comm @ mW1 + mb1   (K=64)
    {
        ull acc[4] = {0ull, 0ull, 0ull, 0ull};
        gemm_rows8<Hd>(acc, mW1, sm + SCR, base, hc);
        const float bb = mb1[hc];
        #pragma unroll
        for (int q = 0; q < 4; q++) {
            const float2 f = unpack2(acc[q]);
            const int r0 = base + 2 * q;
            sm[Z_CM + hc * ST + r0]     = sm[X_CM + hc * ST + r0]     + f.x + bb;
            sm[Z_CM + hc * ST + r0 + 1] = sm[X_CM + hc * ST + r0 + 1] + f.y + bb;
        }
    }
    __syncthreads();

    // gates1 = z @ Wx1 + h @ Wh1 + lb1  (K = 64 + 64, fused dual-stream)
    {
        ull accA[8], accB[8];
        const ull ba = pack2(lb1[p], lb1[p]);
        const ull bb = pack2(lb1[p + 128], lb1[p + 128]);
        #pragma unroll
        for (int q = 0; q < 8; q++) { accA[q] = ba; accB[q] = bb; }
        gemm_gates2_dual(accA, accB, Wx1, Wh1, sm + Z_CM, sm + H_CM, p, rbase);
        store_gates2(sm, accA, accB, p, rbase);
    }
    __syncthreads();

    // LSTM1 (full)
    {
        const int r   = tid & 31;
        const int hcb = (tid >> 5) * 8;
        #pragma unroll
        for (int u = 0; u < 8; u++) {
            const int c = hcb + u;
            const float gi = sm[G_OFF + r * GST + c];
            const float gf = sm[G_OFF + r * GST + 64 + c];
            const float gg = sm[G_OFF + r * GST + 128 + c];
            const float go = sm[G_OFF + r * GST + 192 + c];
            const float z  = sm[Z_CM + c * ST + r];
            const float cold = sm[C_RM + r * HRST + c];
            const float cnew = sigf(gf) * cold + sigf(gi) * tanhf_fast(gg);
            const float hnew = sigf(go) * tanhf_fast(cnew);
            const float hr   = tanhf_fast(hnew + z);
            sm[H_CM + c * ST + r]   = hr;
            sm[H_RM + r * HRST + c] = hr;
            sm[C_RM + r * HRST + c] = cnew;
        }
    }
    __syncthreads();

    // ---- heads + writeback ----
    // logits = h @ actW + actb  (32x16)
    {
        const int lc = tid & 15;
        const int lr = tid >> 4;   // 0..15
        #pragma unroll
        for (int half = 0; half < 2; half++) {
            const int r = lr + 16 * half;
            float s0 = actb[lc], s1 = 0.0f, s2 = 0.0f, s3 = 0.0f;
            #pragma unroll
            for (int k = 0; k < Hd; k += 4) {
                s0 += sm[H_RM + r * HRST + k + 0] * actW[(k + 0) * Ad + lc];
                s1 += sm[H_RM + r * HRST + k + 1] * actW[(k + 1) * Ad + lc];
                s2 += sm[H_RM + r * HRST + k + 2] * actW[(k + 2) * Ad + lc];
                s3 += sm[H_RM + r * HRST + k + 3] * actW[(k + 3) * Ad + lc];
            }
            out[((size_t)b * Nag + r) * Ad + lc] = (s0 + s1) + (s2 + s3);
        }
    }
    // values = h @ valW + valb  (32); bank = (3*tid + kk) % 32, conflict-free
    if (tid < Nag) {
        float s = valb[0];
        #pragma unroll
        for (int kk = 0; kk < Hd; kk++) {
            const int k = (kk + 2 * tid) & 63;
            s += sm[H_RM + tid * HRST + k] * valW[k];
        }
        out[OFF_VAL + (size_t)b * Nag + tid] = s;
    }
    // h, c writeback
    {
        float* oh = out + OFF_H + (size_t)b * (Nag * Hd);
        float* oc = out + OFF_C + (size_t)b * (Nag * Hd);
        #pragma unroll
        for (int u = 0; u < 8; u++) {
            const int idx = u * 256 + tid;
            const int r = idx >> 6, c = idx & 63;
            oh[idx] = sm[H_RM + r * HRST + c];
            oc[idx] = sm[C_RM + r * HRST + c];
        }
    }
}

extern "C" void kernel_launch(void* const* d_in, const int* in_sizes, int n_in,
                              void* d_out, int out_size) {
    const float* obs  = (const float*)d_in[0];
    const float* encW = (const float*)d_in[1];
    const float* encb = (const float*)d_in[2];
    const float* mW0  = (const float*)d_in[3];
    const float* mb0  = (const float*)d_in[4];
    const float* mW1  = (const float*)d_in[5];
    const float* mb1  = (const float*)d_in[6];
    const float* Wx0  = (const float*)d_in[7];
    const float* Wh0  = (const float*)d_in[8];
    const float* lb0  = (const float*)d_in[9];
    const float* Wx1  = (const float*)d_in[10];
    const float* Wh1  = (const float*)d_in[11];
    const float* lb1  = (const float*)d_in[12];
    const float* actW = (const float*)d_in[13];
    const float* actb = (const float*)d_in[14];
    const float* valW = (const float*)d_in[15];
    const float* valb = (const float*)d_in[16];
    float* out = (float*)d_out;

    const size_t shmem = SMEM_FLOATS * sizeof(float);   // 95872 B
    cudaFuncSetAttribute(commnet_kernel,
                         cudaFuncAttributeMaxDynamicSharedMemorySize, (int)shmem);
    commnet_kernel<<<Bsz, 256, shmem>>>(
        obs, encW, encb, mW0, mb0, mW1, mb1,
        Wx0, Wh0, lb0, Wx1, Wh1, lb1,
        actW, actb, valW, valb, out);
}

// round 16
// speedup vs baseline: 1.0317x; 1.0317x over previous
#include <cuda_runtime.h>
#include <cuda_bf16.h>
#include <cstdint>

// CommNetLSTM: B=4096, N=32, OBS=128, H=64, A=16
// One CTA per batch, 3 CTAs/SM. All state col-major in smem; h/c written
// straight to global from LSTM1 (no row-major smem copies).
// Union scratch buffer serves obs -> gates0 -> comm -> gates1.

#define Bsz 4096
#define Nag 32
#define OBSD 128
#define Hd 64
#define Ad 16
#define ST 36       // col-major column stride (144B, 16B-aligned)
#define GST 257     // gates row stride (odd -> conflict-free reads)

#define OFF_VAL  (2097152)
#define OFF_H    (2097152 + 131072)
#define OFF_C    (OFF_H + 8388608)

// smem offsets (floats)
#define X_CM   0              // 64*36
#define H_CM   2304           // 64*36
#define Z_CM   4608           // 64*36
#define C_CM   6912           // 64*36
#define S_OFF  9216           // 64
#define U_OFF  9280           // union: obs 128*36=4608 | comm 64*36 | gates 32*257=8224
#define SMEM_FLOATS (U_OFF + 8224)   // 17504 floats = 70016 B -> 3 CTAs/SM

typedef unsigned long long ull;

__device__ __forceinline__ ull pack2(float lo, float hi) {
    ull r; asm("mov.b64 %0, {%1, %2};" : "=l"(r) : "f"(lo), "f"(hi)); return r;
}
__device__ __forceinline__ float2 unpack2(ull v) {
    float2 f; asm("mov.b64 {%0, %1}, %2;" : "=f"(f.x), "=f"(f.y) : "l"(v)); return f;
}
__device__ __forceinline__ void ffma2(ull& d, ull a, ull b) {
    asm("fma.rn.f32x2 %0, %1, %2, %0;" : "+l"(d) : "l"(a), "l"(b));
}

__device__ __forceinline__ float sigf(float x) {
    return __fdividef(1.0f, 1.0f + __expf(-x));
}
__device__ __forceinline__ float tanhf_fast(float x) {
    return 1.0f - __fdividef(2.0f, __expf(2.0f * x) + 1.0f);
}

// 8-row x 1-col accumulate: acc[4] f32x2 cover rows base..base+7.
template<int K>
__device__ __forceinline__ void gemm_rows8(ull acc[4], const float* __restrict__ W,
                                           const float* vals, int base, int col) {
    #pragma unroll 4
    for (int k = 0; k < K; k++) {
        const float w = W[k * Hd + col];
        const ull wp = pack2(w, w);
        const ulonglong2 v0 = *(const ulonglong2*)&vals[k * ST + base];
        const ulonglong2 v1 = *(const ulonglong2*)&vals[k * ST + base + 4];
        ffma2(acc[0], v0.x, wp);
        ffma2(acc[1], v0.y, wp);
        ffma2(acc[2], v1.x, wp);
        ffma2(acc[3], v1.y, wp);
    }
}

// Gates accumulate: 16 rows (rbase..+15) x 2 cols (p, p+128), K=64.
__device__ __forceinline__ void gemm_gates2(ull accA[8], ull accB[8],
                                            const float* __restrict__ W,
                                            const float* vals, int p, int rbase) {
    #pragma unroll 4
    for (int k = 0; k < Hd; k++) {
        const float wa = W[k * 256 + p];
        const float wb = W[k * 256 + p + 128];
        const ull wpa = pack2(wa, wa);
        const ull wpb = pack2(wb, wb);
        #pragma unroll
        for (int q = 0; q < 4; q++) {
            const ulonglong2 v = *(const ulonglong2*)&vals[k * ST + rbase + q * 4];
            ffma2(accA[2 * q],     v.x, wpa);
            ffma2(accA[2 * q + 1], v.y, wpa);
            ffma2(accB[2 * q],     v.x, wpb);
            ffma2(accB[2 * q + 1], v.y, wpb);
        }
    }
}

__device__ __forceinline__ void store_gates2(float* sm, const ull accA[8],
                                             const ull accB[8], int p, int rbase) {
    #pragma unroll
    for (int q = 0; q < 8; q++) {
        const float2 fa = unpack2(accA[q]);
        const float2 fb = unpack2(accB[q]);
        const int r = rbase + 2 * q;
        sm[U_OFF + r * GST + p]             = fa.x;
        sm[U_OFF + (r + 1) * GST + p]       = fa.y;
        sm[U_OFF + r * GST + p + 128]       = fb.x;
        sm[U_OFF + (r + 1) * GST + p + 128] = fb.y;
    }
}

__global__ void __launch_bounds__(256, 3) commnet_kernel(
    const float* __restrict__ obs,
    const float* __restrict__ encW, const float* __restrict__ encb,
    const float* __restrict__ mW0,  const float* __restrict__ mb0,
    const float* __restrict__ mW1,  const float* __restrict__ mb1,
    const float* __restrict__ Wx0,  const float* __restrict__ Wh0, const float* __restrict__ lb0,
    const float* __restrict__ Wx1,  const float* __restrict__ Wh1, const float* __restrict__ lb1,
    const float* __restrict__ actW, const float* __restrict__ actb,
    const float* __restrict__ valW, const float* __restrict__ valb,
    float* __restrict__ out)
{
    extern __shared__ float sm[];
    const int b   = blockIdx.x;
    const int tid = threadIdx.x;

    // ---- P0: stage obs -> U (col-major k*ST + r) ----
    {
        const int r = tid & 31;
        const int chunk = tid >> 5;
        const float4* src = (const float4*)(obs + (size_t)b * (Nag * OBSD) + r * OBSD);
        #pragma unroll
        for (int q = 0; q < 4; q++) {
            const float4 v = src[chunk * 4 + q];
            const int k = chunk * 16 + q * 4;
            sm[U_OFF + (k + 0) * ST + r] = v.x;
            sm[U_OFF + (k + 1) * ST + r] = v.y;
            sm[U_OFF + (k + 2) * ST + r] = v.z;
            sm[U_OFF + (k + 3) * ST + r] = v.w;
        }
    }
    __syncthreads();

    const int hc    = tid & 63;
    const int base  = (tid >> 6) * 8;
    const int p     = tid & 127;     // gates col pair: p, p+128
    const int rbase = (tid >> 7) * 16;

    // ---- P1: encoder x = tanh(obs @ encW + encb); z0 = x + mb0 ----
    {
        ull acc[4] = {0ull, 0ull, 0ull, 0ull};
        gemm_rows8<OBSD>(acc, encW, sm + U_OFF, base, hc);
        const float eb = encb[hc];
        const float zb = mb0[hc];
        #pragma unroll
        for (int q = 0; q < 4; q++) {
            const float2 f = unpack2(acc[q]);
            const int r0 = base + 2 * q;
            const float x0 = tanhf_fast(f.x + eb);
            const float x1 = tanhf_fast(f.y + eb);
            sm[X_CM + hc * ST + r0]     = x0;
            sm[X_CM + hc * ST + r0 + 1] = x1;
            sm[Z_CM + hc * ST + r0]     = x0 + zb;
            sm[Z_CM + hc * ST + r0 + 1] = x1 + zb;
        }
    }
    __syncthreads();

    // ---- hop 0: gates = z @ Wx0 + lb0  (h=0 -> Wh0 vanishes); obs dead ----
    {
        ull accA[8], accB[8];
        const ull ba = pack2(lb0[p], lb0[p]);
        const ull bb = pack2(lb0[p + 128], lb0[p + 128]);
        #pragma unroll
        for (int q = 0; q < 8; q++) { accA[q] = ba; accB[q] = bb; }
        gemm_gates2(accA, accB, Wx0, sm + Z_CM, p, rbase);
        store_gates2(sm, accA, accB, p, rbase);
    }
    __syncthreads();

    // LSTM0 (c_old = 0): write h, c col-major
    {
        const int r   = tid & 31;
        const int hcb = (tid >> 5) * 8;
        #pragma unroll
        for (int u = 0; u < 8; u++) {
            const int c = hcb + u;
            const float gi = sm[U_OFF + r * GST + c];
            const float gg = sm[U_OFF + r * GST + 128 + c];
            const float go = sm[U_OFF + r * GST + 192 + c];
            const float z  = sm[Z_CM + c * ST + r];
            const float cnew = sigf(gi) * tanhf_fast(gg);
            const float hnew = sigf(go) * tanhf_fast(cnew);
            const float hr   = tanhf_fast(hnew + z);
            sm[H_CM + c * ST + r] = hr;
            sm[C_CM + c * ST + r] = cnew;
        }
    }
    __syncthreads();

    // ---- hop 1: column sums of h (rotated reads: conflict-free) ----
    if (tid < Hd) {
        float s = 0.0f;
        #pragma unroll
        for (int j = 0; j < Nag; j++) {
            const int jj = (j + tid) & 31;
            s += sm[H_CM + tid * ST + jj];
        }
        sm[S_OFF + tid] = s;
    }
    __syncthreads();

    // comm_cm[k][r] = (S[k] - h[k][r]) / 31  -> U (gates0 dead)
    {
        const float inv = 1.0f / 31.0f;
        #pragma unroll
        for (int u = 0; u < 8; u++) {
            const int idx = u * 256 + tid;   // warp-uniform k, lane r
            const int k = idx >> 5, r = idx & 31;
            sm[U_OFF + k * ST + r] = (sm[S_OFF + k] - sm[H_CM + k * ST + r]) * inv;
        }
    }
    __syncthreads();

    // z = x + comm @ mW1 + mb1   (K=64)
    {
        ull acc[4] = {0ull, 0ull, 0ull, 0ull};
        gemm_rows8<Hd>(acc, mW1, sm + U_OFF, base, hc);
        const float bb = mb1[hc];
        #pragma unroll
        for (int q = 0; q < 4; q++) {
            const float2 f = unpack2(acc[q]);
            const int r0 = base + 2 * q;
            sm[Z_CM + hc * ST + r0]     = sm[X_CM + hc * ST + r0]     + f.x + bb;
            sm[Z_CM + hc * ST + r0 + 1] = sm[X_CM + hc * ST + r0 + 1] + f.y + bb;
        }
    }
    __syncthreads();

    // gates1 = z @ Wx1 + h @ Wh1 + lb1  (comm dead -> reuse U)
    {
        ull accA[8], accB[8];
        const ull ba = pack2(lb1[p], lb1[p]);
        const ull bb = pack2(lb1[p + 128], lb1[p + 128]);
        #pragma unroll
        for (int q = 0; q < 8; q++) { accA[q] = ba; accB[q] = bb; }
        gemm_gates2(accA, accB, Wx1, sm + Z_CM, p, rbase);
        gemm_gates2(accA, accB, Wh1, sm + H_CM, p, rbase);
        store_gates2(sm, accA, accB, p, rbase);
    }
    __syncthreads();

    // LSTM1: write h col-major (for heads) + h,c straight to global
    {
        const int r   = tid & 31;
        const int hcb = (tid >> 5) * 8;
        float hv[8], cv[8];
        #pragma unroll
        for (int u = 0; u < 8; u++) {
            const int c = hcb + u;
            const float gi = sm[U_OFF + r * GST + c];
            const float gf = sm[U_OFF + r * GST + 64 + c];
            const float gg = sm[U_OFF + r * GST + 128 + c];
            const float go = sm[U_OFF + r * GST + 192 + c];
            const float z  = sm[Z_CM + c * ST + r];
            const float cold = sm[C_CM + c * ST + r];
            const float cnew = sigf(gf) * cold + sigf(gi) * tanhf_fast(gg);
            const float hnew = sigf(go) * tanhf_fast(cnew);
            const float hr   = tanhf_fast(hnew + z);
            sm[H_CM + c * ST + r] = hr;
            hv[u] = hr;
            cv[u] = cnew;
        }
        float* oh = out + OFF_H + (size_t)b * (Nag * Hd) + r * Hd + hcb;
        float* oc = out + OFF_C + (size_t)b * (Nag * Hd) + r * Hd + hcb;
        *(float4*)(oh)     = make_float4(hv[0], hv[1], hv[2], hv[3]);
        *(float4*)(oh + 4) = make_float4(hv[4], hv[5], hv[6], hv[7]);
        *(float4*)(oc)     = make_float4(cv[0], cv[1], cv[2], cv[3]);
        *(float4*)(oc + 4) = make_float4(cv[4], cv[5], cv[6], cv[7]);
    }
    __syncthreads();

    // ---- heads (read h col-major) ----
    // logits = h @ actW + actb  (32x16); value reads are 2-way broadcast
    {
        const int lc = tid & 15;
        const int lr = tid >> 4;   // 0..15
        #pragma unroll
        for (int half = 0; half < 2; half++) {
            const int r = lr + 16 * half;
            float s0 = actb[lc], s1 = 0.0f, s2 = 0.0f, s3 = 0.0f;
            #pragma unroll
            for (int k = 0; k < Hd; k += 4) {
                s0 += sm[H_CM + (k + 0) * ST + r] * actW[(k + 0) * Ad + lc];
                s1 += sm[H_CM + (k + 1) * ST + r] * actW[(k + 1) * Ad + lc];
                s2 += sm[H_CM + (k + 2) * ST + r] * actW[(k + 2) * Ad + lc];
                s3 += sm[H_CM + (k + 3) * ST + r] * actW[(k + 3) * Ad + lc];
            }
            out[((size_t)b * Nag + r) * Ad + lc] = (s0 + s1) + (s2 + s3);
        }
    }
    // values = h @ valW + valb; bank = (4k + tid) % 32 -> conflict-free
    if (tid < Nag) {
        float s = valb[0];
        #pragma unroll
        for (int k = 0; k < Hd; k++) {
            s += sm[H_CM + k * ST + tid] * valW[k];
        }
        out[OFF_VAL + (size_t)b * Nag + tid] = s;
    }
}

extern "C" void kernel_launch(void* const* d_in, const int* in_sizes, int n_in,
                              void* d_out, int out_size) {
    const float* obs  = (const float*)d_in[0];
    const float* encW = (const float*)d_in[1];
    const float* encb = (const float*)d_in[2];
    const float* mW0  = (const float*)d_in[3];
    const float* mb0  = (const float*)d_in[4];
    const float* mW1  = (const float*)d_in[5];
    const float* mb1  = (const float*)d_in[6];
    const float* Wx0  = (const float*)d_in[7];
    const float* Wh0  = (const float*)d_in[8];
    const float* lb0  = (const float*)d_in[9];
    const float* Wx1  = (const float*)d_in[10];
    const float* Wh1  = (const float*)d_in[11];
    const float* lb1  = (const float*)d_in[12];
    const float* actW = (const float*)d_in[13];
    const float* actb = (const float*)d_in[14];
    const float* valW = (const float*)d_in[15];
    const float* valb = (const float*)d_in[16];
    float* out = (float*)d_out;

    const size_t shmem = SMEM_FLOATS * sizeof(float);   // 70016 B
    cudaFuncSetAttribute(commnet_kernel,
                         cudaFuncAttributeMaxDynamicSharedMemorySize, (int)shmem);
    commnet_kernel<<<Bsz, 256, shmem>>>(
        obs, encW, encb, mW0, mb0, mW1, mb1,
        Wx0, Wh0, lb0, Wx1, Wh1, lb1,
        actW, actb, valW, valb, out);
}